// round 16
// baseline (speedup 1.0000x reference)
#include <cuda_runtime.h>

// ---------------------------------------------------------------------------
// MSRNN: 3-layer GRU-variant.
// Round 15: recurrent step -> TENSOR CORES. Per block the step is a GEMM
// [32 batches x 1024] @ [1024 x 24 gate-rows] done with m16n8k8 tf32 mma
// (3-term hi/lo split, mapping verified in round 14). W hi/lo resident in
// SMEM for the whole layer; h fragments loaded straight from global (no
// SMEM staging). E-GEMMs = proven fp32 gemm_nt. Barrier = r8 atomic.
// ---------------------------------------------------------------------------

#define T0 512
#define T1 511
#define T2 509
#define BB 32
#define HID 1024
#define G3 3072
#define DIN 256

#define M0 (T0*BB)
#define M1 (T1*BB)
#define M2 (T2*BB)

#define OFF1 (T0*BB*DIN)
#define OFF2 (OFF1 + T1*BB*DIN)
#define OFFH (OFF2 + T2*BB*DIN)

#define NBLK 128
#define WST  1028      // W row stride (floats): LDS bank = 4*gid+tig, conflict-free
#define RST  26        // reduction row stride (floats)

// ------------------------- scratch (device globals) ------------------------
__device__ float g_x   [(size_t)T0*BB*DIN];
__device__ float g_ms1 [(size_t)T1*BB*DIN];
__device__ float g_ms2 [(size_t)T2*BB*DIN];
__device__ float g_E0  [(size_t)T0*BB*G3];
__device__ float g_E1  [(size_t)T1*BB*G3];
__device__ float g_E2  [(size_t)T2*BB*G3];
__device__ float g_Y0  [(size_t)T0*BB*HID];
__device__ float g_Y1  [(size_t)T1*BB*HID];
__device__ float g_Y2  [(size_t)T2*BB*HID];
__device__ float g_bs  [3*G3];
__device__ float g_Wsum[(size_t)G3*DIN];

__device__ unsigned int g_cnt = 0;
__device__ volatile unsigned int g_gen = 0;

// ------------------------- packed f32x2 helpers (GEMM) ----------------------
__device__ __forceinline__ unsigned long long pk2(float lo, float hi) {
    unsigned long long r;
    asm("mov.b64 %0, {%1, %2};" : "=l"(r) : "f"(lo), "f"(hi));
    return r;
}
__device__ __forceinline__ void fma2(unsigned long long& d,
                                     unsigned long long a,
                                     unsigned long long b) {
    asm("fma.rn.f32x2 %0, %1, %2, %0;" : "+l"(d) : "l"(a), "l"(b));
}
__device__ __forceinline__ float2 up2(unsigned long long v) {
    float2 f;
    asm("mov.b64 {%0, %1}, %2;" : "=f"(f.x), "=f"(f.y) : "l"(v));
    return f;
}
union U4 {
    float4 f4;
    struct { unsigned long long a, b; } s;
};

// ------------------------- tf32 mma helpers ---------------------------------
__device__ __forceinline__ void mma_tf32(float* d, const unsigned* a, const unsigned* b) {
    asm volatile(
        "mma.sync.aligned.m16n8k8.row.col.f32.tf32.tf32.f32 "
        "{%0,%1,%2,%3}, {%4,%5,%6,%7}, {%8,%9}, {%0,%1,%2,%3};\n"
        : "+f"(d[0]), "+f"(d[1]), "+f"(d[2]), "+f"(d[3])
        : "r"(a[0]), "r"(a[1]), "r"(a[2]), "r"(a[3]), "r"(b[0]), "r"(b[1]));
}
__device__ __forceinline__ void split_hi_lo(float v, float& hi, float& lo) {
    hi = __uint_as_float(__float_as_uint(v) & 0xffffe000u);  // exact in tf32
    lo = v - hi;
}

// ------------------------- prep: transpose + moving means -------------------
__global__ void prep_kernel(const float* __restrict__ in) {
    int i = blockIdx.x * blockDim.x + threadIdx.x;
    if (i >= T0 * BB * DIN) return;
    int d = i % DIN;
    int tb = i / DIN;
    int b = tb % BB;
    int t = tb / BB;
    const float v0 = in[((size_t)b * T0 + t) * DIN + d];
    g_x[i] = v0;
    if (t < T1) {
        float v1 = in[((size_t)b * T0 + t + 1) * DIN + d];
        g_ms1[((size_t)t * BB + b) * DIN + d] = 0.5f * (v0 + v1);
        if (t < T2) {
            float v2 = in[((size_t)b * T0 + t + 2) * DIN + d];
            float v3 = in[((size_t)b * T0 + t + 3) * DIN + d];
            g_ms2[((size_t)t * BB + b) * DIN + d] = 0.25f * (v0 + v1 + v2 + v3);
        }
    }
}

__global__ void bias_wsum_kernel(const float* __restrict__ b0x, const float* __restrict__ b0n,
                                 const float* __restrict__ b1x, const float* __restrict__ b1n,
                                 const float* __restrict__ b2x, const float* __restrict__ b2n,
                                 const float* __restrict__ Wxh0, const float* __restrict__ Wnh0) {
    int i = blockIdx.x * blockDim.x + threadIdx.x;
    if (i < G3) {
        g_bs[i]          = b0x[i] + b0n[i];
        g_bs[G3 + i]     = b1x[i] + b1n[i];
        g_bs[2 * G3 + i] = b2x[i] + b2n[i];
    }
    if (i < G3 * DIN) g_Wsum[i] = Wxh0[i] + Wnh0[i];
}

// ------------------------- GEMM (round-2 proven config) ---------------------
#define GBM 128
#define GBN 64
#define GBK 16

__global__ __launch_bounds__(256) void gemm_nt(
    float* __restrict__ C, const float* __restrict__ A, const float* __restrict__ W,
    const float* __restrict__ bias, int M, int N, int K, int accum)
{
    __shared__ float As[GBK][GBM + 4];
    __shared__ float Bs[GBK][GBN + 4];

    int tid = threadIdx.x;
    int n0 = blockIdx.x * GBN;
    int m0 = blockIdx.y * GBM;
    int ty = tid >> 4, tx = tid & 15;
    int mb = ty * 8, nb = tx * 4;

    unsigned long long acc[4][4];
#pragma unroll
    for (int i = 0; i < 4; i++)
#pragma unroll
        for (int j = 0; j < 4; j++) acc[i][j] = 0ull;

    int arow = tid >> 2;
    int ac4  = (tid & 3) * 4;

    for (int k0 = 0; k0 < K; k0 += GBK) {
#pragma unroll
        for (int r = 0; r < 2; r++) {
            int m = arow + r * 64;
            int gm = m0 + m;
            if (gm > M - 1) gm = M - 1;
            float4 v = *(const float4*)&A[(size_t)gm * K + k0 + ac4];
            As[ac4 + 0][m] = v.x; As[ac4 + 1][m] = v.y;
            As[ac4 + 2][m] = v.z; As[ac4 + 3][m] = v.w;
        }
        {
            int n = arow;
            float4 v = *(const float4*)&W[(size_t)(n0 + n) * K + k0 + ac4];
            Bs[ac4 + 0][n] = v.x; Bs[ac4 + 1][n] = v.y;
            Bs[ac4 + 2][n] = v.z; Bs[ac4 + 3][n] = v.w;
        }
        __syncthreads();
#pragma unroll
        for (int kk = 0; kk < GBK; kk++) {
            U4 a0; a0.f4 = *(const float4*)&As[kk][mb];
            U4 a1; a1.f4 = *(const float4*)&As[kk][mb + 4];
            float4 bv = *(const float4*)&Bs[kk][nb];
            unsigned long long b0 = pk2(bv.x, bv.x), b1 = pk2(bv.y, bv.y);
            unsigned long long b2 = pk2(bv.z, bv.z), b3 = pk2(bv.w, bv.w);
            fma2(acc[0][0], a0.s.a, b0); fma2(acc[0][1], a0.s.a, b1);
            fma2(acc[0][2], a0.s.a, b2); fma2(acc[0][3], a0.s.a, b3);
            fma2(acc[1][0], a0.s.b, b0); fma2(acc[1][1], a0.s.b, b1);
            fma2(acc[1][2], a0.s.b, b2); fma2(acc[1][3], a0.s.b, b3);
            fma2(acc[2][0], a1.s.a, b0); fma2(acc[2][1], a1.s.a, b1);
            fma2(acc[2][2], a1.s.a, b2); fma2(acc[2][3], a1.s.a, b3);
            fma2(acc[3][0], a1.s.b, b0); fma2(acc[3][1], a1.s.b, b1);
            fma2(acc[3][2], a1.s.b, b2); fma2(acc[3][3], a1.s.b, b3);
        }
        __syncthreads();
    }

#pragma unroll
    for (int mp = 0; mp < 4; mp++) {
#pragma unroll
        for (int n = 0; n < 4; n++) {
            float2 v = up2(acc[mp][n]);
            int col = n0 + nb + n;
            int r0 = m0 + mb + 2 * mp;
            float badd = bias ? bias[col] : 0.f;
            if (r0 < M) {
                size_t idx = (size_t)r0 * N + col;
                C[idx] = v.x + (accum ? C[idx] : badd);
            }
            if (r0 + 1 < M) {
                size_t idx = (size_t)(r0 + 1) * N + col;
                C[idx] = v.y + (accum ? C[idx] : badd);
            }
        }
    }
}

// ------------------------- grid barrier (r8 proven) -------------------------
__device__ __forceinline__ void grid_barrier() {
    __syncthreads();
    if (threadIdx.x == 0) {
        __threadfence();
        unsigned int g = g_gen;
        if (atomicAdd(&g_cnt, 1u) == NBLK - 1) {
            g_cnt = 0;
            __threadfence();
            g_gen = g + 1;
        } else {
            while (g_gen == g) { __nanosleep(64); }
            __threadfence();
        }
    }
    __syncthreads();
}

// ------------------------- tensor-core recurrent layer ----------------------
// 128 blocks x 256 threads (8 warps). Block owns 8 hidden units = 24 gate
// rows (n = g*8 + u). Warp w owns K-slice [w*128, (w+1)*128).
// Per step: gh[32x24] = h[32x1024] @ W[24x1024]^T via m16n8k8 tf32 mma,
// 3-term hi/lo split. W hi/lo in SMEM (whole layer); h loaded from global
// directly into fragments. K-reduction: 4 SMEM buffers x 2 rounds.
__global__ __launch_bounds__(256, 1) void layer_tc(
    float* __restrict__ Y, const float* __restrict__ E,
    const float* __restrict__ Whh, const float* __restrict__ bhh, int T)
{
    extern __shared__ float smem[];
    float* Whs = smem;                  // [24][WST] hi
    float* Wls = Whs + 24 * WST;        // [24][WST] lo
    float* red = Wls + 24 * WST;        // [4][32*RST]

    const int tid  = threadIdx.x;
    const int lane = tid & 31, wid = tid >> 5;
    const int gid  = lane >> 2, tig = lane & 3;
    const int kw   = wid * 128;
    const int blk  = blockIdx.x;

    // epilogue cell: batch eb_b, unit eb_u
    const int eb_b = tid & 31, eb_u = tid >> 5;
    const int eb_j = blk * 8 + eb_u;
    const float br = bhh[eb_j];
    const float bi = bhh[HID + eb_j];
    const float bn = bhh[2 * HID + eb_j];

    // ---- load & hi/lo-split W rows: SMEM row r = g*8+uu (== mma n index) ----
#pragma unroll
    for (int i = 0; i < 24; i++) {
        int idx = tid + i * 256;
        int r   = idx >> 8;               // 0..23
        int c4  = (idx & 255) * 4;
        int g = r >> 3, uu = r & 7;
        float4 v = *(const float4*)&Whh[(size_t)(g * HID + blk * 8 + uu) * HID + c4];
        float h, l;
        split_hi_lo(v.x, h, l); Whs[r * WST + c4 + 0] = h; Wls[r * WST + c4 + 0] = l;
        split_hi_lo(v.y, h, l); Whs[r * WST + c4 + 1] = h; Wls[r * WST + c4 + 1] = l;
        split_hi_lo(v.z, h, l); Whs[r * WST + c4 + 2] = h; Wls[r * WST + c4 + 2] = l;
        split_hi_lo(v.w, h, l); Whs[r * WST + c4 + 3] = h; Wls[r * WST + c4 + 3] = l;
    }
    __syncthreads();

    // ---- t = 0: h = 0, 256 threads = 256 cells ----
    {
        const float* Et = E + (size_t)eb_b * G3;
        float er = Et[eb_j];
        float ei = Et[HID + eb_j];
        float en = Et[2 * HID + eb_j];
        float r  = 1.f / (1.f + __expf(-(er + br)));
        float ig = 1.f / (1.f + __expf(-(ei + bi)));
        float n  = tanhf(en + r * bn);
        Y[(size_t)eb_b * HID + eb_j] = n - ig * n;
        grid_barrier();
    }

    for (int t = 1; t < T; t++) {
        const float* hprev = Y + (size_t)(t - 1) * BB * HID;

        // epilogue operand prefetch
        const float* Et = E + ((size_t)t * BB + eb_b) * G3;
        float er = __ldcg(&Et[eb_j]);
        float ei = __ldcg(&Et[HID + eb_j]);
        float en = __ldcg(&Et[2 * HID + eb_j]);
        float hp = __ldcg(&hprev[(size_t)eb_b * HID + eb_j]);

        // ---- A fragments straight from global: av[ms][kt][q]
        //  q0: row ms*16+gid,   col kw+kt*8+tig
        //  q1: row ms*16+gid+8, col kw+kt*8+tig
        //  q2: q0 col +4,  q3: q1 col +4
        float av[2][16][4];
#pragma unroll
        for (int ms = 0; ms < 2; ms++) {
            const float* r0 = hprev + (size_t)(ms * 16 + gid) * HID + kw + tig;
            const float* r1 = hprev + (size_t)(ms * 16 + gid + 8) * HID + kw + tig;
#pragma unroll
            for (int kt = 0; kt < 16; kt++) {
                av[ms][kt][0] = __ldcg(&r0[kt * 8]);
                av[ms][kt][1] = __ldcg(&r1[kt * 8]);
                av[ms][kt][2] = __ldcg(&r0[kt * 8 + 4]);
                av[ms][kt][3] = __ldcg(&r1[kt * 8 + 4]);
            }
        }

        float acc[2][3][4];
#pragma unroll
        for (int ms = 0; ms < 2; ms++)
#pragma unroll
            for (int ns = 0; ns < 3; ns++)
#pragma unroll
                for (int q = 0; q < 4; q++) acc[ms][ns][q] = 0.f;

#pragma unroll
        for (int kt = 0; kt < 16; kt++) {
            unsigned bh[3][2], bl[3][2];
#pragma unroll
            for (int ns = 0; ns < 3; ns++) {
                int nr = (ns * 8 + gid) * WST + kw + kt * 8 + tig;
                bh[ns][0] = __float_as_uint(Whs[nr]);
                bh[ns][1] = __float_as_uint(Whs[nr + 4]);
                bl[ns][0] = __float_as_uint(Wls[nr]);
                bl[ns][1] = __float_as_uint(Wls[nr + 4]);
            }
#pragma unroll
            for (int ms = 0; ms < 2; ms++) {
                unsigned ah[4], al[4];
#pragma unroll
                for (int q = 0; q < 4; q++) {
                    float h, l;
                    split_hi_lo(av[ms][kt][q], h, l);
                    ah[q] = __float_as_uint(h);
                    al[q] = __float_as_uint(l);
                }
#pragma unroll
                for (int ns = 0; ns < 3; ns++) {
                    mma_tf32(acc[ms][ns], ah, bh[ns]);
                    mma_tf32(acc[ms][ns], al, bh[ns]);
                    mma_tf32(acc[ms][ns], ah, bl[ns]);
                }
            }
        }

        // ---- K-reduction: 4 buffers, 2 rounds (warps wid>>2==rnd write buf wid&3)
#pragma unroll
        for (int rnd = 0; rnd < 2; rnd++) {
            if ((wid >> 2) == rnd) {
                float* buf = red + (wid & 3) * (32 * RST);
#pragma unroll
                for (int ms = 0; ms < 2; ms++)
#pragma unroll
                    for (int ns = 0; ns < 3; ns++) {
                        int m0r = (ms * 16 + gid) * RST;
                        int m1r = (ms * 16 + gid + 8) * RST;
                        int c0 = ns * 8 + 2 * tig;
                        if (rnd == 0) {
                            buf[m0r + c0]     = acc[ms][ns][0];
                            buf[m0r + c0 + 1] = acc[ms][ns][1];
                            buf[m1r + c0]     = acc[ms][ns][2];
                            buf[m1r + c0 + 1] = acc[ms][ns][3];
                        } else {
                            buf[m0r + c0]     += acc[ms][ns][0];
                            buf[m0r + c0 + 1] += acc[ms][ns][1];
                            buf[m1r + c0]     += acc[ms][ns][2];
                            buf[m1r + c0 + 1] += acc[ms][ns][3];
                        }
                    }
            }
            __syncthreads();
        }

        // ---- epilogue: cell (eb_b, eb_u); gh col = g*8 + eb_u ----
        float gr = br, gi = bi, gn = bn;
#pragma unroll
        for (int q = 0; q < 4; q++) {
            const float* buf = red + q * (32 * RST) + eb_b * RST;
            gr += buf[0 * 8 + eb_u];
            gi += buf[1 * 8 + eb_u];
            gn += buf[2 * 8 + eb_u];
        }
        float r  = 1.f / (1.f + __expf(-(er + gr)));
        float ig = 1.f / (1.f + __expf(-(ei + gi)));
        float n  = tanhf(en + r * gn);
        Y[(size_t)t * BB * HID + (size_t)eb_b * HID + eb_j] = n + ig * (hp - n);

        if (t != T - 1) grid_barrier();
    }
}

// ------------------------- final hidden-state copy --------------------------
__global__ void copy_hidden(float* __restrict__ out) {
    int i = blockIdx.x * blockDim.x + threadIdx.x;
    if (i >= 3 * BB * HID) return;
    int l = i / (BB * HID);
    int r = i % (BB * HID);
    const float* src;
    if (l == 0)      src = g_Y0 + (size_t)(T0 - 1) * BB * HID;
    else if (l == 1) src = g_Y1 + (size_t)(T1 - 1) * BB * HID;
    else             src = g_Y2 + (size_t)(T2 - 1) * BB * HID;
    out[i] = src[r];
}

// ---------------------------------------------------------------------------
extern "C" void kernel_launch(void* const* d_in, const int* in_sizes, int n_in,
                              void* d_out, int out_size)
{
    const float* inputs = (const float*)d_in[0];
    const float* Wxh0 = (const float*)d_in[1];
    const float* bxh0 = (const float*)d_in[2];
    const float* Whh0 = (const float*)d_in[3];
    const float* bhh0 = (const float*)d_in[4];
    const float* Wnh0 = (const float*)d_in[5];
    const float* bnh0 = (const float*)d_in[6];
    const float* Wxh1 = (const float*)d_in[7];
    const float* bxh1 = (const float*)d_in[8];
    const float* Whh1 = (const float*)d_in[9];
    const float* bhh1 = (const float*)d_in[10];
    const float* Wnh1 = (const float*)d_in[11];
    const float* bnh1 = (const float*)d_in[12];
    const float* Wxh2 = (const float*)d_in[13];
    const float* bxh2 = (const float*)d_in[14];
    const float* Whh2 = (const float*)d_in[15];
    const float* bhh2 = (const float*)d_in[16];
    const float* Wnh2 = (const float*)d_in[17];
    const float* bnh2 = (const float*)d_in[18];
    const float* Wout = (const float*)d_in[19];
    const float* bout = (const float*)d_in[20];

    float *pX, *pM1, *pM2, *pE0, *pE1, *pE2, *pY0, *pY1, *pY2, *pBS, *pWS;
    cudaGetSymbolAddress((void**)&pX,  g_x);
    cudaGetSymbolAddress((void**)&pM1, g_ms1);
    cudaGetSymbolAddress((void**)&pM2, g_ms2);
    cudaGetSymbolAddress((void**)&pE0, g_E0);
    cudaGetSymbolAddress((void**)&pE1, g_E1);
    cudaGetSymbolAddress((void**)&pE2, g_E2);
    cudaGetSymbolAddress((void**)&pY0, g_Y0);
    cudaGetSymbolAddress((void**)&pY1, g_Y1);
    cudaGetSymbolAddress((void**)&pY2, g_Y2);
    cudaGetSymbolAddress((void**)&pBS, g_bs);
    cudaGetSymbolAddress((void**)&pWS, g_Wsum);

    static int smem_set = 0;
    const int LSMEM = (2 * 24 * WST + 4 * 32 * RST) * 4;   // 210,688 B
    if (!smem_set) {
        cudaFuncSetAttribute(layer_tc,
                             cudaFuncAttributeMaxDynamicSharedMemorySize, LSMEM);
        smem_set = 1;
    }

    float* out = (float*)d_out;

    prep_kernel<<<(T0 * BB * DIN + 255) / 256, 256>>>(inputs);
    bias_wsum_kernel<<<(G3 * DIN + 255) / 256, 256>>>(bxh0, bnh0, bxh1, bnh1,
                                                      bxh2, bnh2, Wxh0, Wnh0);

    // ---- layer 0: fused E0 = x @ (Wxh0+Wnh0)^T + bias (ms0 == x) ----
    gemm_nt<<<dim3(G3 / GBN, (M0 + GBM - 1) / GBM), 256>>>(pE0, pX, pWS, pBS, M0, G3, DIN, 0);
    // ---- layer 1 ms-part (independent of Y0) ----
    gemm_nt<<<dim3(G3 / GBN, (M1 + GBM - 1) / GBM), 256>>>(pE1, pM1, Wnh1, pBS + G3, M1, G3, DIN, 0);

    layer_tc<<<NBLK, 256, LSMEM>>>(pY0, pE0, Whh0, bhh0, T0);

    // ---- layer 1 xs-part (Y0 shifted by 1 step), accumulate ----
    gemm_nt<<<dim3(G3 / GBN, (M1 + GBM - 1) / GBM), 256>>>(pE1, pY0 + BB * HID, Wxh1, 0, M1, G3, HID, 1);
    layer_tc<<<NBLK, 256, LSMEM>>>(pY1, pE1, Whh1, bhh1, T1);

    // ---- layer 2 ----
    gemm_nt<<<dim3(G3 / GBN, (M2 + GBM - 1) / GBM), 256>>>(pE2, pM2, Wnh2, pBS + 2 * G3, M2, G3, DIN, 0);
    gemm_nt<<<dim3(G3 / GBN, (M2 + GBM - 1) / GBM), 256>>>(pE2, pY1 + 2 * BB * HID, Wxh2, 0, M2, G3, HID, 1);
    layer_tc<<<NBLK, 256, LSMEM>>>(pY2, pE2, Whh2, bhh2, T2);

    // ---- output projections + hidden states ----
    gemm_nt<<<dim3(DIN / GBN, (M0 + GBM - 1) / GBM), 256>>>(out,        pY0, Wout, bout, M0, DIN, HID, 0);
    gemm_nt<<<dim3(DIN / GBN, (M1 + GBM - 1) / GBM), 256>>>(out + OFF1, pY1, Wout, bout, M1, DIN, HID, 0);
    gemm_nt<<<dim3(DIN / GBN, (M2 + GBM - 1) / GBM), 256>>>(out + OFF2, pY2, Wout, bout, M2, DIN, HID, 0);
    copy_hidden<<<(3 * BB * HID + 255) / 256, 256>>>(out + OFFH);
}

// round 17
// speedup vs baseline: 1.3205x; 1.3205x over previous
#include <cuda_runtime.h>

// ---------------------------------------------------------------------------
// MSRNN: 3-layer GRU-variant.
//   E_l[t] = xs[t] @ Wxh_l^T + ms_l[t] @ Wnh_l^T + bxh_l + bnh_l   (precompute)
//   step:  gh = h @ Whh^T + bhh
//          r = sig(E_r + gh_r); i = sig(E_i + gh_i); n = tanh(E_n + r*gh_n)
//          h' = n + i*(h - n)
// Round 17 = round 8 (best: 28.63 ms) + STREAM OVERLAP: the persistent layer
// kernels occupy 128 of 152 SMs; off-critical-path GEMMs (E1ms, E2ms, out0,
// out1) run on forked streams using the idle SMs, concurrent with the layers.
// Kernels are byte-identical to round 8.
// ---------------------------------------------------------------------------

#define T0 512
#define T1 511
#define T2 509
#define BB 32
#define HID 1024
#define G3 3072
#define DIN 256

#define M0 (T0*BB)
#define M1 (T1*BB)
#define M2 (T2*BB)

#define OFF1 (T0*BB*DIN)
#define OFF2 (OFF1 + T1*BB*DIN)
#define OFFH (OFF2 + T2*BB*DIN)

#define NBLK 128
#define WPAD 1028
#define HPAD 516
#define KCH  512

// ------------------------- scratch (device globals) ------------------------
__device__ float g_x   [(size_t)T0*BB*DIN];
__device__ float g_ms1 [(size_t)T1*BB*DIN];
__device__ float g_ms2 [(size_t)T2*BB*DIN];
__device__ float g_E0  [(size_t)T0*BB*G3];
__device__ float g_E1  [(size_t)T1*BB*G3];
__device__ float g_E2  [(size_t)T2*BB*G3];
__device__ float g_Y0  [(size_t)T0*BB*HID];
__device__ float g_Y1  [(size_t)T1*BB*HID];
__device__ float g_Y2  [(size_t)T2*BB*HID];
__device__ float g_bs  [3*G3];
__device__ float g_Wsum[(size_t)G3*DIN];

__device__ unsigned int g_cnt = 0;
__device__ volatile unsigned int g_gen = 0;

// ------------------------- packed f32x2 helpers -----------------------------
__device__ __forceinline__ unsigned long long pk2(float lo, float hi) {
    unsigned long long r;
    asm("mov.b64 %0, {%1, %2};" : "=l"(r) : "f"(lo), "f"(hi));
    return r;
}
__device__ __forceinline__ void fma2(unsigned long long& d,
                                     unsigned long long a,
                                     unsigned long long b) {
    asm("fma.rn.f32x2 %0, %1, %2, %0;" : "+l"(d) : "l"(a), "l"(b));
}
__device__ __forceinline__ float2 up2(unsigned long long v) {
    float2 f;
    asm("mov.b64 {%0, %1}, %2;" : "=f"(f.x), "=f"(f.y) : "l"(v));
    return f;
}
__device__ __forceinline__ float hadd2(unsigned long long v) {
    float2 f = up2(v);
    return f.x + f.y;
}
union U4 {
    float4 f4;
    struct { unsigned long long a, b; } s;
};

// ------------------------- prep: transpose + moving means -------------------
__global__ void prep_kernel(const float* __restrict__ in) {
    int i = blockIdx.x * blockDim.x + threadIdx.x;
    if (i >= T0 * BB * DIN) return;
    int d = i % DIN;
    int tb = i / DIN;
    int b = tb % BB;
    int t = tb / BB;
    const float v0 = in[((size_t)b * T0 + t) * DIN + d];
    g_x[i] = v0;
    if (t < T1) {
        float v1 = in[((size_t)b * T0 + t + 1) * DIN + d];
        g_ms1[((size_t)t * BB + b) * DIN + d] = 0.5f * (v0 + v1);
        if (t < T2) {
            float v2 = in[((size_t)b * T0 + t + 2) * DIN + d];
            float v3 = in[((size_t)b * T0 + t + 3) * DIN + d];
            g_ms2[((size_t)t * BB + b) * DIN + d] = 0.25f * (v0 + v1 + v2 + v3);
        }
    }
}

// combined biases + Wsum0 = Wxh0 + Wnh0 (layer-0 fusion)
__global__ void bias_wsum_kernel(const float* __restrict__ b0x, const float* __restrict__ b0n,
                                 const float* __restrict__ b1x, const float* __restrict__ b1n,
                                 const float* __restrict__ b2x, const float* __restrict__ b2n,
                                 const float* __restrict__ Wxh0, const float* __restrict__ Wnh0) {
    int i = blockIdx.x * blockDim.x + threadIdx.x;
    if (i < G3) {
        g_bs[i]          = b0x[i] + b0n[i];
        g_bs[G3 + i]     = b1x[i] + b1n[i];
        g_bs[2 * G3 + i] = b2x[i] + b2n[i];
    }
    if (i < G3 * DIN) g_Wsum[i] = Wxh0[i] + Wnh0[i];
}

// ------------------------- GEMM (round-2 proven config) ---------------------
#define GBM 128
#define GBN 64
#define GBK 16

__global__ __launch_bounds__(256) void gemm_nt(
    float* __restrict__ C, const float* __restrict__ A, const float* __restrict__ W,
    const float* __restrict__ bias, int M, int N, int K, int accum)
{
    __shared__ float As[GBK][GBM + 4];
    __shared__ float Bs[GBK][GBN + 4];

    int tid = threadIdx.x;
    int n0 = blockIdx.x * GBN;
    int m0 = blockIdx.y * GBM;
    int ty = tid >> 4, tx = tid & 15;
    int mb = ty * 8, nb = tx * 4;

    unsigned long long acc[4][4];
#pragma unroll
    for (int i = 0; i < 4; i++)
#pragma unroll
        for (int j = 0; j < 4; j++) acc[i][j] = 0ull;

    int arow = tid >> 2;
    int ac4  = (tid & 3) * 4;

    for (int k0 = 0; k0 < K; k0 += GBK) {
#pragma unroll
        for (int r = 0; r < 2; r++) {
            int m = arow + r * 64;
            int gm = m0 + m;
            if (gm > M - 1) gm = M - 1;
            float4 v = *(const float4*)&A[(size_t)gm * K + k0 + ac4];
            As[ac4 + 0][m] = v.x; As[ac4 + 1][m] = v.y;
            As[ac4 + 2][m] = v.z; As[ac4 + 3][m] = v.w;
        }
        {
            int n = arow;
            float4 v = *(const float4*)&W[(size_t)(n0 + n) * K + k0 + ac4];
            Bs[ac4 + 0][n] = v.x; Bs[ac4 + 1][n] = v.y;
            Bs[ac4 + 2][n] = v.z; Bs[ac4 + 3][n] = v.w;
        }
        __syncthreads();
#pragma unroll
        for (int kk = 0; kk < GBK; kk++) {
            U4 a0; a0.f4 = *(const float4*)&As[kk][mb];
            U4 a1; a1.f4 = *(const float4*)&As[kk][mb + 4];
            float4 bv = *(const float4*)&Bs[kk][nb];
            unsigned long long b0 = pk2(bv.x, bv.x), b1 = pk2(bv.y, bv.y);
            unsigned long long b2 = pk2(bv.z, bv.z), b3 = pk2(bv.w, bv.w);
            fma2(acc[0][0], a0.s.a, b0); fma2(acc[0][1], a0.s.a, b1);
            fma2(acc[0][2], a0.s.a, b2); fma2(acc[0][3], a0.s.a, b3);
            fma2(acc[1][0], a0.s.b, b0); fma2(acc[1][1], a0.s.b, b1);
            fma2(acc[1][2], a0.s.b, b2); fma2(acc[1][3], a0.s.b, b3);
            fma2(acc[2][0], a1.s.a, b0); fma2(acc[2][1], a1.s.a, b1);
            fma2(acc[2][2], a1.s.a, b2); fma2(acc[2][3], a1.s.a, b3);
            fma2(acc[3][0], a1.s.b, b0); fma2(acc[3][1], a1.s.b, b1);
            fma2(acc[3][2], a1.s.b, b2); fma2(acc[3][3], a1.s.b, b3);
        }
        __syncthreads();
    }

#pragma unroll
    for (int mp = 0; mp < 4; mp++) {
#pragma unroll
        for (int n = 0; n < 4; n++) {
            float2 v = up2(acc[mp][n]);
            int col = n0 + nb + n;
            int r0 = m0 + mb + 2 * mp;
            float badd = bias ? bias[col] : 0.f;
            if (r0 < M) {
                size_t idx = (size_t)r0 * N + col;
                C[idx] = v.x + (accum ? C[idx] : badd);
            }
            if (r0 + 1 < M) {
                size_t idx = (size_t)(r0 + 1) * N + col;
                C[idx] = v.y + (accum ? C[idx] : badd);
            }
        }
    }
}

// ------------------------- grid barrier (r8 proven) -------------------------
__device__ __forceinline__ void grid_barrier() {
    __syncthreads();
    if (threadIdx.x == 0) {
        __threadfence();
        unsigned int g = g_gen;
        if (atomicAdd(&g_cnt, 1u) == NBLK - 1) {
            g_cnt = 0;
            __threadfence();
            g_gen = g + 1;
        } else {
            while (g_gen == g) { __nanosleep(64); }
            __threadfence();
        }
    }
    __syncthreads();
}

// 128 blocks x 256 threads. Block owns 8 hidden units (24 Whh gate-rows in
// SMEM for the whole layer). warp w = batches 4w..4w+3; u = lane>>2.
// Double-buffered h staging (r8 proven body).
__global__ __launch_bounds__(256, 1) void layer_kernel(
    float* __restrict__ Y, const float* __restrict__ E,
    const float* __restrict__ Whh, const float* __restrict__ bhh, int T)
{
    extern __shared__ float smem[];
    float* Wsh = smem;                      // [24][WPAD]
    float* hs0 = Wsh + 24 * WPAD;           // [32][HPAD]
    float* hs1 = hs0 + 32 * HPAD;           // [32][HPAD]

    int tid  = threadIdx.x;
    int lane = tid & 31;
    int w    = tid >> 5;
    int u    = lane >> 2;
    int b    = 4 * w + (lane & 3);
    int j    = blockIdx.x * 8 + u;

#pragma unroll
    for (int i = 0; i < 24; i++) {
        int idx = tid + i * 256;
        int r   = idx >> 8;
        int c4  = (idx & 255) * 4;
        int gg  = r >> 3, uu = r & 7;
        float4 v = *(const float4*)&Whh[(size_t)(gg * HID + blockIdx.x * 8 + uu) * HID + c4];
        *(float4*)&Wsh[(size_t)r * WPAD + c4] = v;
    }

    const float* Wr = Wsh + (size_t)(0 * 8 + u) * WPAD;
    const float* Wi = Wsh + (size_t)(1 * 8 + u) * WPAD;
    const float* Wn = Wsh + (size_t)(2 * 8 + u) * WPAD;
    const float* hrow0 = hs0 + (size_t)b * HPAD;
    const float* hrow1 = hs1 + (size_t)b * HPAD;

    float br = bhh[j];
    float bi = bhh[HID + j];
    float bn = bhh[2 * HID + j];

    __syncthreads();

    // ---- t = 0: h = 0 ----
    {
        const float* Et = E + (size_t)b * G3;
        float er = Et[j];
        float ei = Et[HID + j];
        float en = Et[2 * HID + j];
        float r  = 1.f / (1.f + __expf(-(er + br)));
        float ig = 1.f / (1.f + __expf(-(ei + bi)));
        float n  = tanhf(en + r * bn);
        Y[(size_t)b * HID + j] = n - ig * n;
        grid_barrier();
    }

    for (int t = 1; t < T; t++) {
        const float* hprev = Y + (size_t)(t - 1) * BB * HID;

        const float* Et = E + ((size_t)t * BB + b) * G3;
        float er = __ldcg(&Et[j]);
        float ei = __ldcg(&Et[HID + j]);
        float en = __ldcg(&Et[2 * HID + j]);
        float hp = __ldcg(&hprev[(size_t)b * HID + j]);

#pragma unroll
        for (int i = 0; i < 16; i++) {
            int idx  = tid + i * 256;
            int hb   = idx >> 7;
            int koff = (idx & 127) * 4;
            float4 v = __ldcg((const float4*)&hprev[(size_t)hb * HID + koff]);
            *(float4*)&hs0[(size_t)hb * HPAD + koff] = v;
        }
        float4 p[16];
#pragma unroll
        for (int i = 0; i < 16; i++) {
            int idx  = tid + i * 256;
            int hb   = idx >> 7;
            int koff = (idx & 127) * 4;
            p[i] = __ldcg((const float4*)&hprev[(size_t)hb * HID + KCH + koff]);
        }
        __syncthreads();

        unsigned long long aR0 = 0, aR1 = 0, aI0 = 0, aI1 = 0, aN0 = 0, aN1 = 0;

#pragma unroll 8
        for (int kk = 0; kk < KCH; kk += 8) {
            U4 h0; h0.f4 = *(const float4*)&hrow0[kk];
            U4 h1; h1.f4 = *(const float4*)&hrow0[kk + 4];
            U4 r0; r0.f4 = *(const float4*)&Wr[kk];
            U4 r1; r1.f4 = *(const float4*)&Wr[kk + 4];
            U4 i0; i0.f4 = *(const float4*)&Wi[kk];
            U4 i1; i1.f4 = *(const float4*)&Wi[kk + 4];
            U4 n0; n0.f4 = *(const float4*)&Wn[kk];
            U4 n1; n1.f4 = *(const float4*)&Wn[kk + 4];
            fma2(aR0, h0.s.a, r0.s.a); fma2(aR0, h0.s.b, r0.s.b);
            fma2(aR1, h1.s.a, r1.s.a); fma2(aR1, h1.s.b, r1.s.b);
            fma2(aI0, h0.s.a, i0.s.a); fma2(aI0, h0.s.b, i0.s.b);
            fma2(aI1, h1.s.a, i1.s.a); fma2(aI1, h1.s.b, i1.s.b);
            fma2(aN0, h0.s.a, n0.s.a); fma2(aN0, h0.s.b, n0.s.b);
            fma2(aN1, h1.s.a, n1.s.a); fma2(aN1, h1.s.b, n1.s.b);
        }

#pragma unroll
        for (int i = 0; i < 16; i++) {
            int idx  = tid + i * 256;
            int hb   = idx >> 7;
            int koff = (idx & 127) * 4;
            *(float4*)&hs1[(size_t)hb * HPAD + koff] = p[i];
        }
        __syncthreads();

#pragma unroll 8
        for (int kk = 0; kk < KCH; kk += 8) {
            U4 h0; h0.f4 = *(const float4*)&hrow1[kk];
            U4 h1; h1.f4 = *(const float4*)&hrow1[kk + 4];
            U4 r0; r0.f4 = *(const float4*)&Wr[KCH + kk];
            U4 r1; r1.f4 = *(const float4*)&Wr[KCH + kk + 4];
            U4 i0; i0.f4 = *(const float4*)&Wi[KCH + kk];
            U4 i1; i1.f4 = *(const float4*)&Wi[KCH + kk + 4];
            U4 n0; n0.f4 = *(const float4*)&Wn[KCH + kk];
            U4 n1; n1.f4 = *(const float4*)&Wn[KCH + kk + 4];
            fma2(aR0, h0.s.a, r0.s.a); fma2(aR0, h0.s.b, r0.s.b);
            fma2(aR1, h1.s.a, r1.s.a); fma2(aR1, h1.s.b, r1.s.b);
            fma2(aI0, h0.s.a, i0.s.a); fma2(aI0, h0.s.b, i0.s.b);
            fma2(aI1, h1.s.a, i1.s.a); fma2(aI1, h1.s.b, i1.s.b);
            fma2(aN0, h0.s.a, n0.s.a); fma2(aN0, h0.s.b, n0.s.b);
            fma2(aN1, h1.s.a, n1.s.a); fma2(aN1, h1.s.b, n1.s.b);
        }

        float gr = hadd2(aR0) + hadd2(aR1) + br;
        float gi = hadd2(aI0) + hadd2(aI1) + bi;
        float gn = hadd2(aN0) + hadd2(aN1) + bn;

        float r  = 1.f / (1.f + __expf(-(er + gr)));
        float ig = 1.f / (1.f + __expf(-(ei + gi)));
        float n  = tanhf(en + r * gn);
        Y[(size_t)t * BB * HID + (size_t)b * HID + j] = n + ig * (hp - n);

        if (t != T - 1) grid_barrier();
    }
}

// ------------------------- final hidden-state copy --------------------------
__global__ void copy_hidden(float* __restrict__ out) {
    int i = blockIdx.x * blockDim.x + threadIdx.x;
    if (i >= 3 * BB * HID) return;
    int l = i / (BB * HID);
    int r = i % (BB * HID);
    const float* src;
    if (l == 0)      src = g_Y0 + (size_t)(T0 - 1) * BB * HID;
    else if (l == 1) src = g_Y1 + (size_t)(T1 - 1) * BB * HID;
    else             src = g_Y2 + (size_t)(T2 - 1) * BB * HID;
    out[i] = src[r];
}

// ---------------------------------------------------------------------------
extern "C" void kernel_launch(void* const* d_in, const int* in_sizes, int n_in,
                              void* d_out, int out_size)
{
    const float* inputs = (const float*)d_in[0];
    const float* Wxh0 = (const float*)d_in[1];
    const float* bxh0 = (const float*)d_in[2];
    const float* Whh0 = (const float*)d_in[3];
    const float* bhh0 = (const float*)d_in[4];
    const float* Wnh0 = (const float*)d_in[5];
    const float* bnh0 = (const float*)d_in[6];
    const float* Wxh1 = (const float*)d_in[7];
    const float* bxh1 = (const float*)d_in[8];
    const float* Whh1 = (const float*)d_in[9];
    const float* bhh1 = (const float*)d_in[10];
    const float* Wnh1 = (const float*)d_in[11];
    const float* bnh1 = (const float*)d_in[12];
    const float* Wxh2 = (const float*)d_in[13];
    const float* bxh2 = (const float*)d_in[14];
    const float* Whh2 = (const float*)d_in[15];
    const float* bhh2 = (const float*)d_in[16];
    const float* Wnh2 = (const float*)d_in[17];
    const float* bnh2 = (const float*)d_in[18];
    const float* Wout = (const float*)d_in[19];
    const float* bout = (const float*)d_in[20];

    float *pX, *pM1, *pM2, *pE0, *pE1, *pE2, *pY0, *pY1, *pY2, *pBS, *pWS;
    cudaGetSymbolAddress((void**)&pX,  g_x);
    cudaGetSymbolAddress((void**)&pM1, g_ms1);
    cudaGetSymbolAddress((void**)&pM2, g_ms2);
    cudaGetSymbolAddress((void**)&pE0, g_E0);
    cudaGetSymbolAddress((void**)&pE1, g_E1);
    cudaGetSymbolAddress((void**)&pE2, g_E2);
    cudaGetSymbolAddress((void**)&pY0, g_Y0);
    cudaGetSymbolAddress((void**)&pY1, g_Y1);
    cudaGetSymbolAddress((void**)&pY2, g_Y2);
    cudaGetSymbolAddress((void**)&pBS, g_bs);
    cudaGetSymbolAddress((void**)&pWS, g_Wsum);

    // static-once resources (same pattern as smem attribute below)
    static int init_done = 0;
    static cudaStream_t sA, sB;
    static cudaEvent_t evPrep, evMs, evL0, evL1, evOut0, evOut1;
    const int LSMEM = (24 * WPAD + 64 * HPAD) * 4;   // 230,784 B
    if (!init_done) {
        cudaFuncSetAttribute(layer_kernel,
                             cudaFuncAttributeMaxDynamicSharedMemorySize, LSMEM);
        cudaStreamCreateWithFlags(&sA, cudaStreamNonBlocking);
        cudaStreamCreateWithFlags(&sB, cudaStreamNonBlocking);
        cudaEventCreateWithFlags(&evPrep, cudaEventDisableTiming);
        cudaEventCreateWithFlags(&evMs,   cudaEventDisableTiming);
        cudaEventCreateWithFlags(&evL0,   cudaEventDisableTiming);
        cudaEventCreateWithFlags(&evL1,   cudaEventDisableTiming);
        cudaEventCreateWithFlags(&evOut0, cudaEventDisableTiming);
        cudaEventCreateWithFlags(&evOut1, cudaEventDisableTiming);
        init_done = 1;
    }

    float* out = (float*)d_out;

    // ---- main stream: prep + bias/Wsum ----
    prep_kernel<<<(T0 * BB * DIN + 255) / 256, 256>>>(inputs);
    bias_wsum_kernel<<<(G3 * DIN + 255) / 256, 256>>>(bxh0, bnh0, bxh1, bnh1,
                                                      bxh2, bnh2, Wxh0, Wnh0);
    cudaEventRecord(evPrep, 0);

    // ---- side stream A: ms-part GEMMs for layers 1 & 2 (independent of Y0).
    // These run on the ~24 SMs the persistent layer kernels leave idle.
    cudaStreamWaitEvent(sA, evPrep, 0);
    gemm_nt<<<dim3(G3 / GBN, (M1 + GBM - 1) / GBM), 256, 0, sA>>>(
        pE1, pM1, Wnh1, pBS + G3, M1, G3, DIN, 0);
    gemm_nt<<<dim3(G3 / GBN, (M2 + GBM - 1) / GBM), 256, 0, sA>>>(
        pE2, pM2, Wnh2, pBS + 2 * G3, M2, G3, DIN, 0);
    cudaEventRecord(evMs, sA);

    // ---- main: layer 0 (fused E0 = x @ (Wxh0+Wnh0)^T + bias; ms0 == x) ----
    gemm_nt<<<dim3(G3 / GBN, (M0 + GBM - 1) / GBM), 256>>>(pE0, pX, pWS, pBS, M0, G3, DIN, 0);
    layer_kernel<<<NBLK, 256, LSMEM>>>(pY0, pE0, Whh0, bhh0, T0);
    cudaEventRecord(evL0, 0);

    // ---- side stream B: out-proj of Y0 (runs during E1xs + layer1) ----
    cudaStreamWaitEvent(sB, evL0, 0);
    gemm_nt<<<dim3(DIN / GBN, (M0 + GBM - 1) / GBM), 256, 0, sB>>>(
        out, pY0, Wout, bout, M0, DIN, HID, 0);
    cudaEventRecord(evOut0, sB);

    // ---- main: layer 1 (xs = Y0 shifted by 1 step; accumulate onto ms-part)
    cudaStreamWaitEvent(0, evMs, 0);   // E1 ms-part must be written first
    gemm_nt<<<dim3(G3 / GBN, (M1 + GBM - 1) / GBM), 256>>>(
        pE1, pY0 + BB * HID, Wxh1, 0, M1, G3, HID, 1);
    layer_kernel<<<NBLK, 256, LSMEM>>>(pY1, pE1, Whh1, bhh1, T1);
    cudaEventRecord(evL1, 0);

    // ---- side stream B: out-proj of Y1 (runs during E2xs + layer2) ----
    cudaStreamWaitEvent(sB, evL1, 0);
    gemm_nt<<<dim3(DIN / GBN, (M1 + GBM - 1) / GBM), 256, 0, sB>>>(
        out + OFF1, pY1, Wout, bout, M1, DIN, HID, 0);
    cudaEventRecord(evOut1, sB);

    // ---- main: layer 2 ----
    gemm_nt<<<dim3(G3 / GBN, (M2 + GBM - 1) / GBM), 256>>>(
        pE2, pY1 + 2 * BB * HID, Wxh2, 0, M2, G3, HID, 1);
    layer_kernel<<<NBLK, 256, LSMEM>>>(pY2, pE2, Whh2, bhh2, T2);

    // ---- main: out-proj of Y2 + hidden states; join side streams ----
    gemm_nt<<<dim3(DIN / GBN, (M2 + GBM - 1) / GBM), 256>>>(
        out + OFF2, pY2, Wout, bout, M2, DIN, HID, 0);
    copy_hidden<<<(3 * BB * HID + 255) / 256, 256>>>(out + OFFH);
    cudaStreamWaitEvent(0, evOut0, 0);
    cudaStreamWaitEvent(0, evOut1, 0);
}